// round 1
// baseline (speedup 1.0000x reference)
#include <cuda_runtime.h>
#include <math.h>
#include <stdint.h>

#define BB   1024      // batch rows
#define NN   8192      // samples per row
#define MM   1800      // fold period (bpm*n/1800 -> period 1800)
#define NB   140       // bpm bins
#define NBP  144       // padded bins
#define TABW 288       // sin plane [144] + cos plane [144]
#define NCH  9         // m-chunks
#define MCH  200       // m per chunk (9*200 = 1800)

// ---------------- device scratch (no allocations allowed) ----------------
__device__ float d_hann[NN];
__device__ float d_tab[MM * TABW];            // [m][0..143]=sin, [m][144..287]=cos
__device__ float d_fold[(size_t)BB * MM];     // folded hann-weighted pred
__device__ float d_part[(size_t)NCH * BB * 2 * NBP]; // DFT partials per chunk
__device__ float d_tl[BB];                    // per-row (1 - pearson)
__device__ float d_fl[BB];                    // per-row (ce + kl)

// ---------------- warp helpers ----------------
__device__ __forceinline__ float wsum(float v) {
    #pragma unroll
    for (int o = 16; o; o >>= 1) v += __shfl_down_sync(0xffffffffu, v, o);
    return v;
}
__device__ __forceinline__ float wallsum(float v) {
    #pragma unroll
    for (int o = 16; o; o >>= 1) v += __shfl_xor_sync(0xffffffffu, v, o);
    return v;
}
__device__ __forceinline__ float wallmax(float v) {
    #pragma unroll
    for (int o = 16; o; o >>= 1) v = fmaxf(v, __shfl_xor_sync(0xffffffffu, v, o));
    return v;
}

// ---------------- K1: build hann + sin/cos tables (double precision) ----------------
__global__ void k_init() {
    int idx = blockIdx.x * 256 + threadIdx.x;
    const int T1 = MM * NBP;                   // 259200 table slots
    if (idx < T1) {
        int m = idx / NBP, k = idx % NBP;
        float s = 0.f, c = 0.f;
        if (k < NB) {
            long long r = ((long long)(40 + k) * (long long)m) % MM;
            double ang = (double)r * (2.0 * M_PI / 1800.0);
            double ds, dc; sincos(ang, &ds, &dc);
            s = (float)ds; c = (float)dc;
        }
        d_tab[m * TABW + k]       = s;
        d_tab[m * TABW + NBP + k] = c;
    } else if (idx < T1 + NN) {
        int n = idx - T1;
        d_hann[n] = (float)(0.5 - 0.5 * cos(2.0 * M_PI * (double)n / 8191.0));
    }
}

// ---------------- K2: per-row pearson sums + hann-weighted fold ----------------
__global__ void __launch_bounds__(256) k_fold(const float* __restrict__ x,
                                              const float* __restrict__ y) {
    __shared__ float shx[NN];          // 32 KB
    __shared__ float red[8][5];
    int b = blockIdx.x;
    int tid = threadIdx.x;
    int lane = tid & 31, warp = tid >> 5;

    const float* xr = x + (size_t)b * NN;
    const float* yr = y + (size_t)b * NN;

    float sx = 0.f, sy = 0.f, sxy = 0.f, sxx = 0.f, syy = 0.f;
    for (int n = tid; n < NN; n += 256) {
        float xv = xr[n], yv = yr[n];
        sx  += xv;        sy  += yv;
        sxy += xv * yv;   sxx += xv * xv;  syy += yv * yv;
        shx[n] = xv * d_hann[n];
    }
    sx = wsum(sx); sy = wsum(sy); sxy = wsum(sxy); sxx = wsum(sxx); syy = wsum(syy);
    if (lane == 0) { red[warp][0]=sx; red[warp][1]=sy; red[warp][2]=sxy; red[warp][3]=sxx; red[warp][4]=syy; }
    __syncthreads();

    // fold: g[m] = sum_j shx[m + 1800 j]
    for (int m = tid; m < MM; m += 256) {
        float g = shx[m] + shx[m + 1800] + shx[m + 3600] + shx[m + 5400];
        if (m < NN - 4 * 1800) g += shx[m + 7200];   // 992 leftovers
        d_fold[(size_t)b * MM + m] = g;
    }

    if (tid == 0) {
        double SX=0, SY=0, SXY=0, SXX=0, SYY=0;
        #pragma unroll
        for (int w = 0; w < 8; w++) {
            SX += red[w][0]; SY += red[w][1]; SXY += red[w][2];
            SXX += red[w][3]; SYY += red[w][4];
        }
        double num = (double)NN * SXY - SX * SY;
        double den = sqrt(((double)NN * SXX - SX * SX) * ((double)NN * SYY - SY * SY));
        d_tl[b] = (float)(1.0 - num / den);
    }
}

// ---------------- K3: folded NUDFT as register-tiled fp32 GEMM ----------------
// grid: (32 row-tiles, 9 m-chunks), block 288 = (36 bin-groups x 8 row-groups)
// thread tile: 4 rows x 4 bins x {sin,cos} = 32 accumulators
__global__ void __launch_bounds__(288) k_dft() {
    __shared__ float sTab[8 * TABW];   // 9.2 KB: 8 m x (sin144|cos144)
    __shared__ float sG[8 * 36];       // 8 m x 32 rows (stride 36, 16B-aligned rows)

    int tile  = blockIdx.x;            // 0..31  -> rows [tile*32, tile*32+32)
    int chunk = blockIdx.y;            // 0..8   -> m in [chunk*200, +200)
    int tid = threadIdx.x;
    int tx = tid % 36;                 // bin group: bins 4tx..4tx+3 (tx=35 -> padded zeros)
    int ty = tid / 36;                 // row group: rows 4ty..4ty+3 (within tile)

    float aS[4][4] = {}, aC[4][4] = {};
    int rowBase = tile * 32;
    int mBase = chunk * MCH;

    for (int step = 0; step < MCH / 8; step++) {
        int m0 = mBase + step * 8;
        __syncthreads();
        #pragma unroll
        for (int i = 0; i < 8; i++)
            sTab[i * TABW + tid] = d_tab[(size_t)(m0 + i) * TABW + tid];
        if (tid < 256) {
            int r = tid >> 3, mi = tid & 7;
            sG[mi * 36 + r] = d_fold[(size_t)(rowBase + r) * MM + m0 + mi];
        }
        __syncthreads();

        #pragma unroll
        for (int mi = 0; mi < 8; mi++) {
            float4 gv = *(const float4*)&sG[mi * 36 + 4 * ty];
            float4 sv = *(const float4*)&sTab[mi * TABW + 4 * tx];
            float4 cv = *(const float4*)&sTab[mi * TABW + NBP + 4 * tx];
            float gA[4] = {gv.x, gv.y, gv.z, gv.w};
            float sA[4] = {sv.x, sv.y, sv.z, sv.w};
            float cA[4] = {cv.x, cv.y, cv.z, cv.w};
            #pragma unroll
            for (int r = 0; r < 4; r++) {
                #pragma unroll
                for (int kb = 0; kb < 4; kb++) {
                    aS[r][kb] = fmaf(gA[r], sA[kb], aS[r][kb]);
                    aC[r][kb] = fmaf(gA[r], cA[kb], aC[r][kb]);
                }
            }
        }
    }

    // deterministic partials (no atomics)
    #pragma unroll
    for (int r = 0; r < 4; r++) {
        int row = rowBase + 4 * ty + r;
        size_t base = (((size_t)chunk * BB + row) * 2) * NBP;
        float4 vs = make_float4(aS[r][0], aS[r][1], aS[r][2], aS[r][3]);
        float4 vc = make_float4(aC[r][0], aC[r][1], aC[r][2], aC[r][3]);
        *(float4*)&d_part[base + 4 * tx]       = vs;
        *(float4*)&d_part[base + NBP + 4 * tx] = vc;
    }
}

// ---------------- K4: per-row spectrum -> ce + kl ----------------
// one warp per row; 8 warps/block; 128 blocks
__global__ void __launch_bounds__(256) k_rowloss(const int* __restrict__ hr) {
    int lane = threadIdx.x & 31, warp = threadIdx.x >> 5;
    int row = blockIdx.x * 8 + warp;

    float ca[5]; bool valid[5];
    float tot = 0.f;
    #pragma unroll
    for (int j = 0; j < 5; j++) {
        int k = lane + 32 * j;
        valid[j] = (k < NB);
        float s = 0.f, c = 0.f;
        if (valid[j]) {
            #pragma unroll
            for (int ch = 0; ch < NCH; ch++) {
                size_t base = (((size_t)ch * BB + row) * 2) * NBP;
                s += d_part[base + k];
                c += d_part[base + NBP + k];
            }
        }
        ca[j] = s * s + c * c;
        if (valid[j]) tot += ca[j];
    }
    tot = wallsum(tot);

    float logits[5];
    float mx = -1e30f;
    #pragma unroll
    for (int j = 0; j < 5; j++) {
        logits[j] = ca[j] / tot;
        if (valid[j]) mx = fmaxf(mx, logits[j]);
    }
    mx = wallmax(mx);
    float se = 0.f;
    #pragma unroll
    for (int j = 0; j < 5; j++)
        if (valid[j]) se += expf(logits[j] - mx);
    se = wallsum(se);
    float lse = mx + logf(se);

    int h = hr[row];
    float lh = 0.f;
    #pragma unroll
    for (int j = 0; j < 5; j++) {
        int k = lane + 32 * j;
        if (valid[j] && k == h) lh = logits[j];
    }
    lh = wallsum(lh);
    float ce = lse - lh;

    float hf = (float)h;
    float klp = 0.f;
    #pragma unroll
    for (int j = 0; j < 5; j++) {
        if (valid[j]) {
            int k = lane + 32 * j;
            float dd = (float)k - hf;
            float t = expf(-0.5f * dd * dd) * 0.3989422804014327f;
            t = fmaxf(t, 1e-15f);
            float logp = logits[j] - lse;
            klp += expf(t) * (t - logp);
        }
    }
    klp = wallsum(klp);
    if (lane == 0) d_fl[row] = ce + klp / (float)NB;
}

// ---------------- K5: final scalar ----------------
__global__ void __launch_bounds__(1024) k_final(const int* __restrict__ epoch_p,
                                                float* __restrict__ out) {
    __shared__ float r1[32], r2[32];
    int tid = threadIdx.x, lane = tid & 31, warp = tid >> 5;
    float a = d_tl[tid], c = d_fl[tid];
    a = wsum(a); c = wsum(c);
    if (lane == 0) { r1[warp] = a; r2[warp] = c; }
    __syncthreads();
    if (warp == 0) {
        a = wsum(r1[lane]);
        c = wsum(r2[lane]);
        if (lane == 0) {
            double tl = (double)a / (double)BB;
            double fl = (double)c / (double)BB;
            int epoch = epoch_p[0];
            double alpha, beta;
            if (epoch > 25) { alpha = 0.05; beta = 2.0; }
            else {
                alpha = 0.1 * pow(0.5, (double)epoch / 25.0);
                beta  = pow(2.0, (double)epoch / 25.0);
            }
            out[0] = (float)(alpha * tl + beta * fl);
        }
    }
}

// ---------------- launch ----------------
extern "C" void kernel_launch(void* const* d_in, const int* in_sizes, int n_in,
                              void* d_out, int out_size) {
    const int*   epoch_p = nullptr;
    const float* xp = nullptr;
    const float* yp = nullptr;
    const int*   hrp = nullptr;
    for (int i = 0; i < n_in; i++) {
        if (in_sizes[i] == 1 && !epoch_p) epoch_p = (const int*)d_in[i];
        else if (in_sizes[i] == BB * NN) { if (!xp) xp = (const float*)d_in[i]; else yp = (const float*)d_in[i]; }
        else if (in_sizes[i] == BB) hrp = (const int*)d_in[i];
    }
    float* out = (float*)d_out;

    int initWork = MM * NBP + NN;
    k_init<<<(initWork + 255) / 256, 256>>>();
    k_fold<<<BB, 256>>>(xp, yp);
    k_dft<<<dim3(32, NCH), 288>>>();
    k_rowloss<<<BB / 8, 256>>>(hrp);
    k_final<<<1, 1024>>>(epoch_p, out);
    (void)out_size;
}

// round 2
// speedup vs baseline: 1.0313x; 1.0313x over previous
#include <cuda_runtime.h>
#include <math.h>
#include <stdint.h>

#define BB   1024      // batch rows
#define NN   8192      // samples per row
#define MM   1800      // fold period (bpm*n/1800 -> period 1800)
#define NB   140       // bpm bins
#define NBP  144       // padded bins
#define NCH  9         // m-chunks
#define MCH  200       // m per chunk (9*200 = 1800)

// ---------------- device scratch ----------------
__device__ float  d_hann[NN];
__device__ float  d_tab[MM * 2 * NBP];                 // [m][bin] interleaved (sin,cos)
__device__ float  d_fold[(size_t)BB * MM];             // folded hann-weighted pred
__device__ float2 d_part[(size_t)NCH * BB * NBP];      // per-chunk DFT partials (s,c)
__device__ float2 d_spec[(size_t)BB * NBP];            // chunk-summed spectrum
__device__ float  d_tl[BB];                            // per-row (1 - pearson)
__device__ float  d_fl[BB];                            // per-row (ce + kl)

// ---------------- f32x2 helpers ----------------
__device__ __forceinline__ unsigned long long pk2(float lo, float hi) {
    unsigned long long r;
    asm("mov.b64 %0, {%1, %2};" : "=l"(r) : "f"(lo), "f"(hi));
    return r;
}
__device__ __forceinline__ void upk2(float& lo, float& hi, unsigned long long v) {
    asm("mov.b64 {%0, %1}, %2;" : "=f"(lo), "=f"(hi) : "l"(v));
}
__device__ __forceinline__ void fma2(unsigned long long& d, unsigned long long a,
                                     unsigned long long b) {
    asm("fma.rn.f32x2 %0, %1, %2, %0;" : "+l"(d) : "l"(a), "l"(b));
}

// ---------------- warp helpers ----------------
__device__ __forceinline__ float wsum(float v) {
    #pragma unroll
    for (int o = 16; o; o >>= 1) v += __shfl_down_sync(0xffffffffu, v, o);
    return v;
}
__device__ __forceinline__ float wallsum(float v) {
    #pragma unroll
    for (int o = 16; o; o >>= 1) v += __shfl_xor_sync(0xffffffffu, v, o);
    return v;
}
__device__ __forceinline__ float wallmax(float v) {
    #pragma unroll
    for (int o = 16; o; o >>= 1) v = fmaxf(v, __shfl_xor_sync(0xffffffffu, v, o));
    return v;
}

// ---------------- K1: tables (float; integer-reduced args so fp32 is exact enough) ----
__global__ void __launch_bounds__(256) k_init() {
    int idx = blockIdx.x * 256 + threadIdx.x;
    const int T1 = MM * NBP;
    if (idx < T1) {
        int m = idx / NBP, k = idx % NBP;
        float s = 0.f, c = 0.f;
        if (k < NB) {
            int r = (int)(((long long)(40 + k) * (long long)m) % MM);
            float ang = (float)r * 3.4906585e-3f;      // 2*pi/1800
            sincosf(ang, &s, &c);
        }
        d_tab[m * (2 * NBP) + 2 * k]     = s;
        d_tab[m * (2 * NBP) + 2 * k + 1] = c;
    } else if (idx < T1 + NN) {
        int n = idx - T1;
        d_hann[n] = 0.5f - 0.5f * cosf((float)n * 7.671087e-4f);  // 2*pi/8191
    }
}

// ---------------- K2: pearson sums + hann-weighted fold ----------------
__global__ void __launch_bounds__(256) k_fold(const float* __restrict__ x,
                                              const float* __restrict__ y) {
    __shared__ float shx[NN];          // 32 KB
    __shared__ float red[8][5];
    int b = blockIdx.x;
    int tid = threadIdx.x;
    int lane = tid & 31, warp = tid >> 5;

    const float* xr = x + (size_t)b * NN;
    const float* yr = y + (size_t)b * NN;

    float sx = 0.f, sy = 0.f, sxy = 0.f, sxx = 0.f, syy = 0.f;
    for (int n = tid; n < NN; n += 256) {
        float xv = xr[n], yv = yr[n];
        sx  += xv;        sy  += yv;
        sxy += xv * yv;   sxx += xv * xv;  syy += yv * yv;
        shx[n] = xv * d_hann[n];
    }
    sx = wsum(sx); sy = wsum(sy); sxy = wsum(sxy); sxx = wsum(sxx); syy = wsum(syy);
    if (lane == 0) { red[warp][0]=sx; red[warp][1]=sy; red[warp][2]=sxy; red[warp][3]=sxx; red[warp][4]=syy; }
    __syncthreads();

    for (int m = tid; m < MM; m += 256) {
        float g = shx[m] + shx[m + 1800] + shx[m + 3600] + shx[m + 5400];
        if (m < NN - 4 * 1800) g += shx[m + 7200];
        d_fold[(size_t)b * MM + m] = g;
    }

    if (tid == 0) {
        double SX=0, SY=0, SXY=0, SXX=0, SYY=0;
        #pragma unroll
        for (int w = 0; w < 8; w++) {
            SX += red[w][0]; SY += red[w][1]; SXY += red[w][2];
            SXX += red[w][3]; SYY += red[w][4];
        }
        double num = (double)NN * SXY - SX * SY;
        double den = sqrt(((double)NN * SXX - SX * SX) * ((double)NN * SYY - SY * SY));
        d_tl[b] = (float)(1.0 - num / den);
    }
}

// ---------------- K3: folded NUDFT, f32x2 (sin,cos)-packed GEMM ----------------
// grid (32 row-tiles, 9 m-chunks), block 144 = 36 tx * 4 ty
// thread tile: 8 rows x 4 bins, bins strided by 36 (conflict-free LDS.64 table loads)
__global__ void __launch_bounds__(144, 2) k_dft() {
    __shared__ float sTab[8 * 2 * NBP];   // 8 m x 144 bins x (s,c) = 9216 B
    __shared__ float sG[8 * 36];          // 8 m x 32 rows (stride 36)

    int tile  = blockIdx.x;
    int chunk = blockIdx.y;
    int tid = threadIdx.x;
    int tx = tid % 36;                 // bins tx, tx+36, tx+72, tx+108
    int ty = tid / 36;                 // rows 8*ty .. 8*ty+7

    int rowBase = tile * 32;
    int mBase = chunk * MCH;

    unsigned long long acc[8][4] = {};

    for (int step = 0; step < MCH / 8; step++) {
        int m0 = mBase + step * 8;
        __syncthreads();
        // fill table: 8 rows x 288 floats = 576 float4
        {
            const float4* gt = (const float4*)(d_tab + (size_t)m0 * (2 * NBP));
            float4* st = (float4*)sTab;
            #pragma unroll
            for (int i = 0; i < 4; i++) st[tid + i * 144] = gt[tid + i * 144];
        }
        // fill g: 8 m x 32 rows
        for (int i = tid; i < 256; i += 144) {
            int r = i >> 3, mi = i & 7;
            sG[mi * 36 + r] = d_fold[(size_t)(rowBase + r) * MM + m0 + mi];
        }
        __syncthreads();

        #pragma unroll
        for (int mi = 0; mi < 8; mi++) {
            float4 g0 = *(const float4*)&sG[mi * 36 + 8 * ty];
            float4 g1 = *(const float4*)&sG[mi * 36 + 8 * ty + 4];
            const unsigned long long* trow =
                (const unsigned long long*)&sTab[mi * (2 * NBP)];
            unsigned long long p0 = trow[tx];
            unsigned long long p1 = trow[tx + 36];
            unsigned long long p2 = trow[tx + 72];
            unsigned long long p3 = trow[tx + 108];
            float gr[8] = {g0.x, g0.y, g0.z, g0.w, g1.x, g1.y, g1.z, g1.w};
            #pragma unroll
            for (int r = 0; r < 8; r++) {
                unsigned long long g2 = pk2(gr[r], gr[r]);
                fma2(acc[r][0], g2, p0);
                fma2(acc[r][1], g2, p1);
                fma2(acc[r][2], g2, p2);
                fma2(acc[r][3], g2, p3);
            }
        }
    }

    // deterministic partials: [chunk][row][bin] (s,c)
    #pragma unroll
    for (int r = 0; r < 8; r++) {
        int row = rowBase + 8 * ty + r;
        unsigned long long* dst =
            (unsigned long long*)(d_part + ((size_t)chunk * BB + row) * NBP);
        dst[tx]       = acc[r][0];
        dst[tx + 36]  = acc[r][1];
        dst[tx + 72]  = acc[r][2];
        dst[tx + 108] = acc[r][3];
    }
}

// ---------------- K3b: sum chunk partials -> spectrum ----------------
__global__ void __launch_bounds__(256) k_reduce() {
    int idx = blockIdx.x * 256 + threadIdx.x;   // < BB*NBP
    if (idx < BB * NBP) {
        float s = 0.f, c = 0.f;
        #pragma unroll
        for (int ch = 0; ch < NCH; ch++) {
            float2 v = d_part[(size_t)ch * BB * NBP + idx];
            s += v.x; c += v.y;
        }
        d_spec[idx] = make_float2(s, c);
    }
}

// ---------------- K4: per-row spectrum -> ce + kl (one warp / row) ----------------
__global__ void __launch_bounds__(256) k_rowloss(const int* __restrict__ hr) {
    int lane = threadIdx.x & 31, warp = threadIdx.x >> 5;
    int row = blockIdx.x * 8 + warp;

    float ca[5]; bool valid[5];
    float tot = 0.f;
    #pragma unroll
    for (int j = 0; j < 5; j++) {
        int k = lane + 32 * j;
        valid[j] = (k < NB);
        float2 v = valid[j] ? d_spec[(size_t)row * NBP + k] : make_float2(0.f, 0.f);
        ca[j] = v.x * v.x + v.y * v.y;
        if (valid[j]) tot += ca[j];
    }
    tot = wallsum(tot);

    float logits[5];
    float mx = -1e30f;
    #pragma unroll
    for (int j = 0; j < 5; j++) {
        logits[j] = ca[j] / tot;
        if (valid[j]) mx = fmaxf(mx, logits[j]);
    }
    mx = wallmax(mx);
    float se = 0.f;
    #pragma unroll
    for (int j = 0; j < 5; j++)
        if (valid[j]) se += expf(logits[j] - mx);
    se = wallsum(se);
    float lse = mx + logf(se);

    int h = hr[row];
    float lh = 0.f;
    #pragma unroll
    for (int j = 0; j < 5; j++) {
        int k = lane + 32 * j;
        if (valid[j] && k == h) lh = logits[j];
    }
    lh = wallsum(lh);
    float ce = lse - lh;

    float hf = (float)h;
    float klp = 0.f;
    #pragma unroll
    for (int j = 0; j < 5; j++) {
        if (valid[j]) {
            int k = lane + 32 * j;
            float dd = (float)k - hf;
            float t = expf(-0.5f * dd * dd) * 0.3989422804014327f;
            t = fmaxf(t, 1e-15f);
            float logp = logits[j] - lse;
            klp += expf(t) * (t - logp);
        }
    }
    klp = wallsum(klp);
    if (lane == 0) d_fl[row] = ce + klp / (float)NB;
}

// ---------------- K5: final scalar ----------------
__global__ void __launch_bounds__(1024) k_final(const int* __restrict__ epoch_p,
                                                float* __restrict__ out) {
    __shared__ float r1[32], r2[32];
    int tid = threadIdx.x, lane = tid & 31, warp = tid >> 5;
    float a = d_tl[tid], c = d_fl[tid];
    a = wsum(a); c = wsum(c);
    if (lane == 0) { r1[warp] = a; r2[warp] = c; }
    __syncthreads();
    if (warp == 0) {
        a = wsum(r1[lane]);
        c = wsum(r2[lane]);
        if (lane == 0) {
            double tl = (double)a / (double)BB;
            double fl = (double)c / (double)BB;
            int epoch = epoch_p[0];
            double alpha, beta;
            if (epoch > 25) { alpha = 0.05; beta = 2.0; }
            else {
                alpha = 0.1 * pow(0.5, (double)epoch / 25.0);
                beta  = pow(2.0, (double)epoch / 25.0);
            }
            out[0] = (float)(alpha * tl + beta * fl);
        }
    }
}

// ---------------- launch ----------------
extern "C" void kernel_launch(void* const* d_in, const int* in_sizes, int n_in,
                              void* d_out, int out_size) {
    const int*   epoch_p = nullptr;
    const float* xp = nullptr;
    const float* yp = nullptr;
    const int*   hrp = nullptr;
    for (int i = 0; i < n_in; i++) {
        if (in_sizes[i] == 1 && !epoch_p) epoch_p = (const int*)d_in[i];
        else if (in_sizes[i] == BB * NN) { if (!xp) xp = (const float*)d_in[i]; else yp = (const float*)d_in[i]; }
        else if (in_sizes[i] == BB) hrp = (const int*)d_in[i];
    }
    float* out = (float*)d_out;

    int initWork = MM * NBP + NN;
    k_init<<<(initWork + 255) / 256, 256>>>();
    k_fold<<<BB, 256>>>(xp, yp);
    k_dft<<<dim3(32, NCH), 144>>>();
    k_reduce<<<(BB * NBP + 255) / 256, 256>>>();
    k_rowloss<<<BB / 8, 256>>>(hrp);
    k_final<<<1, 1024>>>(epoch_p, out);
    (void)out_size;
}